// round 7
// baseline (speedup 1.0000x reference)
#include <cuda_runtime.h>
#include <cuda_fp16.h>
#include <cstdint>

// Problem constants
#define MDIM 32
#define KDIM 8192
#define NDIM 28672
#define N_TILE 128                // n-columns per CTA (4 warps x 32)
#define THREADS 128
#define KSPLIT 8
#define K_PER_SPLIT (KDIM / KSPLIT)       // 1024
#define S_K 32                            // weight k-rows per pipeline stage
#define NBUF 2                            // per-warp cp.async ring depth
#define TOTAL_STAGES (K_PER_SPLIT / S_K)  // 32
#define K_CHUNK 256                       // act chunk (8 stages)
#define APAD 8
#define WPITCH 36                         // int32 words per k-row in warp tile (32+4)
#define STAGE_WORDS (S_K * WPITCH)        // 1152 words = 4608 B
#define NBLOCKS (NDIM / N_TILE)           // 224

#define SA_BYTES (MDIM * (K_CHUNK + APAD) * 2)            // 16896
#define SW_BYTES (4 * NBUF * STAGE_WORDS * 4)             // 36864
#define SMEM_BYTES (SA_BYTES + SW_BYTES)                  // 53760

// Scratch: split-K fp32 partials (29.4 MB), fp16 act copy, arrival counters
__device__ float  g_partial[KSPLIT][MDIM * NDIM];
__device__ __half g_actH[MDIM * KDIM];
__device__ int    g_counter[NBLOCKS];

// ---------------------------------------------------------------------------
__device__ __forceinline__ void mma16816(float c[4], const uint32_t a[4],
                                         uint32_t b0, uint32_t b1) {
    asm volatile(
        "mma.sync.aligned.m16n8k16.row.col.f32.f16.f16.f32 "
        "{%0,%1,%2,%3}, {%4,%5,%6,%7}, {%8,%9}, {%0,%1,%2,%3};"
        : "+f"(c[0]), "+f"(c[1]), "+f"(c[2]), "+f"(c[3])
        : "r"(a[0]), "r"(a[1]), "r"(a[2]), "r"(a[3]), "r"(b0), "r"(b1));
}

__device__ __forceinline__ void ldsm_x4(uint32_t a[4], uint32_t smem_addr) {
    asm volatile(
        "ldmatrix.sync.aligned.m8n8.x4.shared.b16 {%0,%1,%2,%3}, [%4];"
        : "=r"(a[0]), "=r"(a[1]), "=r"(a[2]), "=r"(a[3])
        : "r"(smem_addr));
}

// Two int32 weights (in [-127,127]) -> packed half2 {w0, w1}. Exact.
__device__ __forceinline__ uint32_t cvt_w2(int w0, int w1) {
    uint32_t t, h;
    asm("prmt.b32 %0, %1, %2, 0x0400;" : "=r"(t) : "r"(w0), "r"(w1));
    asm("lop3.b32 %0, %1, %2, %3, 0x6A;"            // (a & b) ^ c
        : "=r"(h) : "r"(t), "n"(0x00FF00FF), "n"(0x64806480));
    const uint32_t bias = 0x64806480u;               // half2(1152, 1152)
    __half2 hv = __hsub2(*reinterpret_cast<__half2*>(&h),
                         *reinterpret_cast<const __half2*>(&bias));
    return *reinterpret_cast<uint32_t*>(&hv);
}

__device__ __forceinline__ void cp_async16(uint32_t smem_dst, const void* gsrc) {
    asm volatile("cp.async.cg.shared.global [%0], [%1], 16;\n"
                 :: "r"(smem_dst), "l"(gsrc));
}
__device__ __forceinline__ void cp_commit() {
    asm volatile("cp.async.commit_group;");
}
__device__ __forceinline__ void cp_wait1() {
    asm volatile("cp.async.wait_group 1;");
}

// ---------------------------------------------------------------------------
__global__ void __launch_bounds__(THREADS)
dq_gemm_partial_kernel(const int*   __restrict__ weight,  // int32 (int8 values)
                       const float* __restrict__ scale,
                       float*       __restrict__ out)
{
    extern __shared__ char smem[];
    __half* sA = reinterpret_cast<__half*>(smem);                 // [32][264]
    int*    sWall = reinterpret_cast<int*>(smem + SA_BYTES);      // [4][NBUF][1152]
    __shared__ int sFlag;

    const int tid  = threadIdx.x;
    const int warp = tid >> 5;
    const int lane = tid & 31;
    const int gid  = lane >> 2;   // 0..7
    const int tig  = lane & 3;    // 0..3

    const int nblk  = blockIdx.x * N_TILE;
    const int kz    = blockIdx.y;
    const int kbase = kz * K_PER_SPLIT;

    float acc[2][4][4];
#pragma unroll
    for (int i = 0; i < 2; i++)
#pragma unroll
        for (int j = 0; j < 4; j++)
#pragma unroll
            for (int c = 0; c < 4; c++) acc[i][j][c] = 0.0f;

    // A-side ldmatrix addresses
    const int lrow = lane & 15;
    const int lcol = (lane >> 4) * 8;
    const uint32_t sA_base = (uint32_t)__cvta_generic_to_shared(sA);
    const uint32_t rowbytesA = (K_CHUNK + APAD) * 2;
    const uint32_t addrA0 = sA_base + lrow * rowbytesA + lcol * 2;         // m 0-15
    const uint32_t addrA1 = sA_base + (16 + lrow) * rowbytesA + lcol * 2;  // m 16-31

    // Per-warp weight cp.async: warp owns cols [warp*32, warp*32+32) (128B lines!)
    // lane -> row (lane>>3)+4j, col-chunk (lane&7)*4 within the warp's 32 cols.
    const int crow = lane >> 3;         // 0..3
    const int ccol = (lane & 7) * 4;    // 0,4,...,28
    const int* wsrc = weight + (size_t)crow * NDIM + nblk + warp * 32 + ccol;
    int* sWw = sWall + warp * (NBUF * STAGE_WORDS);
    const uint32_t sWw_base = (uint32_t)__cvta_generic_to_shared(sWw);
    const uint32_t cp_dst0 = sWw_base + (uint32_t)((crow * WPITCH + ccol) * 4);

    // B-fragment LDS base word offset within a stage buffer
    const int boff = 2 * tig * WPITCH + gid;

    auto cp_stage = [&](int k0, int buf) {
        const int* src = wsrc + (size_t)k0 * NDIM;
        const uint32_t dst = cp_dst0 + (uint32_t)(buf * STAGE_WORDS * 4);
#pragma unroll
        for (int j = 0; j < 8; j++)
            cp_async16(dst + j * (4 * WPITCH * 4), src + (size_t)(4 * j) * NDIM);
    };
    auto load_act = [&](int kc) {
#pragma unroll
        for (int i = tid; i < MDIM * (K_CHUNK / 8); i += THREADS) {
            const int r = i >> 5;       // K_CHUNK/8 == 32
            const int c = i & 31;
            *reinterpret_cast<int4*>(&sA[r * (K_CHUNK + APAD) + c * 8]) =
                *reinterpret_cast<const int4*>(g_actH + (size_t)r * KDIM + kc + c * 8);
        }
    };
    auto compute_stage = [&](int buf, int choff) {
        const int* wb = sWw + buf * STAGE_WORDS;
#pragma unroll
        for (int kk = 0; kk < S_K; kk += 16) {
            uint32_t afrag0[4], afrag1[4];
            ldsm_x4(afrag0, addrA0 + (choff + kk) * 2);
            ldsm_x4(afrag1, addrA1 + (choff + kk) * 2);
#pragma unroll
            for (int nt = 0; nt < 4; nt++) {
                const int* p = wb + kk * WPITCH + boff + nt * 8;
                const int w0 = p[0];
                const int w1 = p[WPITCH];
                const int w2 = p[8 * WPITCH];
                const int w3 = p[9 * WPITCH];
                const uint32_t b0 = cvt_w2(w0, w1);
                const uint32_t b1 = cvt_w2(w2, w3);
                mma16816(acc[0][nt], afrag0, b0, b1);
                mma16816(acc[1][nt], afrag1, b0, b1);
            }
        }
    };

    // --- prologue: 2 per-warp weight stages in flight + act chunk 0
    cp_stage(kbase + 0 * S_K, 0); cp_commit();
    cp_stage(kbase + 1 * S_K, 1); cp_commit();
    load_act(kbase);
    __syncthreads();

#pragma unroll 1
    for (int st = 0; st < TOTAL_STAGES; st++) {
        if ((st & 7) == 0 && st > 0) {
            __syncthreads();                  // all warps done with prev act chunk
            load_act(kbase + st * S_K);
            __syncthreads();
        }
        cp_wait1();                           // group st (== stage st) resident
        compute_stage(st & 1, (st & 7) * S_K);
        const int pf = st + 2;
        if (pf < TOTAL_STAGES) cp_stage(kbase + pf * S_K, st & 1);
        cp_commit();                          // commit every iter (empty at tail)
    }

    // --- write unscaled partials
    float* part = g_partial[kz];
#pragma unroll
    for (int mt = 0; mt < 2; mt++) {
#pragma unroll
        for (int nt = 0; nt < 4; nt++) {
            const int col = nblk + warp * 32 + nt * 8 + 2 * tig;
            const int r0 = mt * 16 + gid;
#pragma unroll
            for (int hr = 0; hr < 2; hr++) {
                const int r = r0 + hr * 8;
                float2 o;
                o.x = acc[mt][nt][hr * 2 + 0];
                o.y = acc[mt][nt][hr * 2 + 1];
                *reinterpret_cast<float2*>(part + (size_t)r * NDIM + col) = o;
            }
        }
    }

    // --- fused split-K finish: last CTA of this n-block reduces its slab
    __syncthreads();                          // all partial STGs ordered before atomic
    if (tid == 0) {
        __threadfence();                      // release
        const int old = atomicAdd(&g_counter[blockIdx.x], 1);
        sFlag = (old == KSPLIT - 1);
    }
    __syncthreads();
    if (sFlag) {
        __threadfence();                      // acquire
#pragma unroll
        for (int i = 0; i < 8; i++) {
            const int lin = i * THREADS + tid;        // 0..1023 float4s
            const int row = lin >> 5;                 // 32 float4 per row
            const int c4  = lin & 31;
            const int col = nblk + c4 * 4;
            const size_t addr = (size_t)row * NDIM + col;

            float4 s = *reinterpret_cast<const float4*>(&g_partial[0][addr]);
#pragma unroll
            for (int p = 1; p < KSPLIT; p++) {
                const float4 q = *reinterpret_cast<const float4*>(&g_partial[p][addr]);
                s.x += q.x; s.y += q.y; s.z += q.z; s.w += q.w;
            }
            const float4 sc = *reinterpret_cast<const float4*>(scale + col);
            float4 o;
            o.x = __half2float(__float2half_rn(s.x * sc.x));
            o.y = __half2float(__float2half_rn(s.y * sc.y));
            o.z = __half2float(__float2half_rn(s.z * sc.z));
            o.w = __half2float(__float2half_rn(s.w * sc.w));
            *reinterpret_cast<float4*>(out + addr) = o;
        }
    }
}

// ---------------------------------------------------------------------------
// One-shot act f32 -> fp16 (lossless) + zero the arrival counters.
__global__ void __launch_bounds__(256)
act_cvt_kernel(const float* __restrict__ act) {
    const int i = blockIdx.x * blockDim.x + threadIdx.x;   // per float4
    if (i < NBLOCKS) g_counter[i] = 0;
    const float4 v = reinterpret_cast<const float4*>(act)[i];
    __half2* dst = reinterpret_cast<__half2*>(g_actH) + i * 2;
    dst[0] = __floats2half2_rn(v.x, v.y);
    dst[1] = __floats2half2_rn(v.z, v.w);
}

// ---------------------------------------------------------------------------
extern "C" void kernel_launch(void* const* d_in, const int* in_sizes, int n_in,
                              void* d_out, int out_size) {
    const float* act    = (const float*)d_in[0];   // [32, 8192] f32
    const int*   weight = (const int*)d_in[1];     // [8192, 28672] int32
    const float* scale  = (const float*)d_in[2];   // [28672] f32
    float*       out    = (float*)d_out;           // [32, 28672] f32

    cudaFuncSetAttribute(dq_gemm_partial_kernel,
                         cudaFuncAttributeMaxDynamicSharedMemorySize, SMEM_BYTES);

    act_cvt_kernel<<<(MDIM * KDIM / 4) / 256, 256>>>(act);

    dim3 grid(NBLOCKS, KSPLIT);
    dq_gemm_partial_kernel<<<grid, THREADS, SMEM_BYTES>>>(weight, scale, out);
}

// round 8
// speedup vs baseline: 1.0706x; 1.0706x over previous
#include <cuda_runtime.h>
#include <cuda_fp16.h>
#include <cstdint>

// Problem constants
#define MDIM 32
#define KDIM 8192
#define NDIM 28672
#define N_TILE 128                // n-columns per CTA (4 warps x 32)
#define THREADS 128
#define KSPLIT 8
#define K_PER_SPLIT (KDIM / KSPLIT)       // 1024
#define S_K 16                            // weight k-rows per pipeline stage
#define NBUF 3                            // per-warp cp.async ring depth
#define TOTAL_STAGES (K_PER_SPLIT / S_K)  // 64
#define K_CHUNK 256                       // act chunk (16 stages)
#define APAD 8
#define WPITCH 36                         // int32 words per k-row in warp tile (32+4)
#define STAGE_WORDS (S_K * WPITCH)        // 576 words = 2304 B
#define NBLOCKS (NDIM / N_TILE)           // 224

// Scratch: split-K fp32 partials (29.4 MB) + arrival counters
__device__ float g_partial[KSPLIT][MDIM * NDIM];
__device__ int   g_counter[NBLOCKS];      // zero-init; self-resetting per launch

// ---------------------------------------------------------------------------
__device__ __forceinline__ void mma16816(float c[4], const uint32_t a[4],
                                         uint32_t b0, uint32_t b1) {
    asm volatile(
        "mma.sync.aligned.m16n8k16.row.col.f32.f16.f16.f32 "
        "{%0,%1,%2,%3}, {%4,%5,%6,%7}, {%8,%9}, {%0,%1,%2,%3};"
        : "+f"(c[0]), "+f"(c[1]), "+f"(c[2]), "+f"(c[3])
        : "r"(a[0]), "r"(a[1]), "r"(a[2]), "r"(a[3]), "r"(b0), "r"(b1));
}

__device__ __forceinline__ void ldsm_x4(uint32_t a[4], uint32_t smem_addr) {
    asm volatile(
        "ldmatrix.sync.aligned.m8n8.x4.shared.b16 {%0,%1,%2,%3}, [%4];"
        : "=r"(a[0]), "=r"(a[1]), "=r"(a[2]), "=r"(a[3])
        : "r"(smem_addr));
}

// Two int32 weights (in [-127,127]) -> packed half2 {w0, w1}. Exact.
__device__ __forceinline__ uint32_t cvt_w2(int w0, int w1) {
    uint32_t t, h;
    asm("prmt.b32 %0, %1, %2, 0x0400;" : "=r"(t) : "r"(w0), "r"(w1));
    asm("lop3.b32 %0, %1, %2, %3, 0x6A;"            // (a & b) ^ c
        : "=r"(h) : "r"(t), "n"(0x00FF00FF), "n"(0x64806480));
    const uint32_t bias = 0x64806480u;               // half2(1152, 1152)
    __half2 hv = __hsub2(*reinterpret_cast<__half2*>(&h),
                         *reinterpret_cast<const __half2*>(&bias));
    return *reinterpret_cast<uint32_t*>(&hv);
}

__device__ __forceinline__ void cp_async16(uint32_t smem_dst, const void* gsrc) {
    asm volatile("cp.async.cg.shared.global [%0], [%1], 16;\n"
                 :: "r"(smem_dst), "l"(gsrc));
}
__device__ __forceinline__ void cp_commit() {
    asm volatile("cp.async.commit_group;");
}
__device__ __forceinline__ void cp_wait2() {
    asm volatile("cp.async.wait_group 2;");
}

// ---------------------------------------------------------------------------
__global__ void __launch_bounds__(THREADS)
dq_gemm_kernel(const float* __restrict__ act,     // f32 (fp16 values)
               const int*   __restrict__ weight,  // int32 (int8 values)
               const float* __restrict__ scale,
               float*       __restrict__ out)
{
    __shared__ __half sA[MDIM][K_CHUNK + APAD];              // 16.9 KB
    __shared__ int    sW[4][NBUF][STAGE_WORDS];              // 27.6 KB
    __shared__ int    sFlag;

    const int tid  = threadIdx.x;
    const int warp = tid >> 5;
    const int lane = tid & 31;
    const int gid  = lane >> 2;   // 0..7
    const int tig  = lane & 3;    // 0..3

    const int nblk  = blockIdx.x * N_TILE;
    const int kz    = blockIdx.y;
    const int kbase = kz * K_PER_SPLIT;

    float acc[2][4][4];
#pragma unroll
    for (int i = 0; i < 2; i++)
#pragma unroll
        for (int j = 0; j < 4; j++)
#pragma unroll
            for (int c = 0; c < 4; c++) acc[i][j][c] = 0.0f;

    // A-side ldmatrix addresses
    const int lrow = lane & 15;
    const int lcol = (lane >> 4) * 8;
    const uint32_t sA_base = (uint32_t)__cvta_generic_to_shared(&sA[0][0]);
    const uint32_t rowbytesA = (K_CHUNK + APAD) * 2;
    const uint32_t addrA0 = sA_base + lrow * rowbytesA + lcol * 2;         // m 0-15
    const uint32_t addrA1 = sA_base + (16 + lrow) * rowbytesA + lcol * 2;  // m 16-31

    // Per-warp weight cp.async: warp owns cols [warp*32, warp*32+32) (128B lines).
    // lane -> row (lane>>3)+4j (j<4 => 16 rows), col-chunk (lane&7)*4.
    const int crow = lane >> 3;         // 0..3
    const int ccol = (lane & 7) * 4;    // 0,4,...,28
    const int* wsrc = weight + (size_t)crow * NDIM + nblk + warp * 32 + ccol;
    const uint32_t sWw_base = (uint32_t)__cvta_generic_to_shared(&sW[warp][0][0]);
    const uint32_t cp_dst0 = sWw_base + (uint32_t)((crow * WPITCH + ccol) * 4);
    const int* wbase = &sW[warp][0][0];

    // B-fragment LDS base word offset within a stage buffer (conflict-free:
    // bank = (8*tig + gid + 8*nt) mod 32, all distinct per nt)
    const int boff = 2 * tig * WPITCH + gid;

    auto cp_stage = [&](int st) {
        const int* src = wsrc + (size_t)(kbase + st * S_K) * NDIM;
        const uint32_t dst = cp_dst0 + (uint32_t)((st % NBUF) * STAGE_WORDS * 4);
#pragma unroll
        for (int j = 0; j < 4; j++)
            cp_async16(dst + j * (4 * WPITCH * 4), src + (size_t)(4 * j) * NDIM);
    };
    auto load_act = [&](int kc) {
#pragma unroll
        for (int i = tid; i < MDIM * (K_CHUNK / 4); i += THREADS) {
            const int r = i >> 6;           // K_CHUNK/4 == 64
            const int c = i & 63;
            const float4 v = *reinterpret_cast<const float4*>(
                act + (size_t)r * KDIM + kc + c * 4);
            __half2* dst = reinterpret_cast<__half2*>(&sA[r][c * 4]);
            dst[0] = __floats2half2_rn(v.x, v.y);
            dst[1] = __floats2half2_rn(v.z, v.w);
        }
    };
    auto compute_stage = [&](int buf, int choff) {
        const int* wb = wbase + buf * STAGE_WORDS;
        uint32_t afrag0[4], afrag1[4];
        ldsm_x4(afrag0, addrA0 + choff * 2);
        ldsm_x4(afrag1, addrA1 + choff * 2);
#pragma unroll
        for (int nt = 0; nt < 4; nt++) {
            const int* p = wb + boff + nt * 8;
            const int w0 = p[0];
            const int w1 = p[WPITCH];
            const int w2 = p[8 * WPITCH];
            const int w3 = p[9 * WPITCH];
            const uint32_t b0 = cvt_w2(w0, w1);
            const uint32_t b1 = cvt_w2(w2, w3);
            mma16816(acc[0][nt], afrag0, b0, b1);
            mma16816(acc[1][nt], afrag1, b0, b1);
        }
    };

    // --- prologue: 2 per-warp weight stages in flight + act chunk 0
    cp_stage(0); cp_commit();
    cp_stage(1); cp_commit();
    load_act(kbase);
    __syncthreads();

#pragma unroll 1
    for (int st = 0; st < TOTAL_STAGES; st++) {
        if (st + 2 < TOTAL_STAGES) cp_stage(st + 2);    // prefetch FIRST
        cp_commit();                                    // (empty at tail)
        if ((st & 15) == 0 && st > 0) {                 // act chunk swap
            __syncthreads();
            load_act(kbase + st * S_K);
            __syncthreads();
        }
        cp_wait2();                                     // stage st resident
        compute_stage(st % NBUF, (st & 15) * S_K);
    }

    // --- write unscaled partials
    float* part = g_partial[kz];
#pragma unroll
    for (int mt = 0; mt < 2; mt++) {
#pragma unroll
        for (int nt = 0; nt < 4; nt++) {
            const int col = nblk + warp * 32 + nt * 8 + 2 * tig;
            const int r0 = mt * 16 + gid;
#pragma unroll
            for (int hr = 0; hr < 2; hr++) {
                const int r = r0 + hr * 8;
                float2 o;
                o.x = acc[mt][nt][hr * 2 + 0];
                o.y = acc[mt][nt][hr * 2 + 1];
                *reinterpret_cast<float2*>(part + (size_t)r * NDIM + col) = o;
            }
        }
    }

    // --- fused split-K finish: last CTA of this n-block reduces its slab
    __syncthreads();
    if (tid == 0) {
        __threadfence();                      // release partials
        const int old = atomicAdd(&g_counter[blockIdx.x], 1);
        sFlag = (old == KSPLIT - 1);
    }
    __syncthreads();
    if (sFlag) {
        __threadfence();                      // acquire partials
#pragma unroll
        for (int i = 0; i < 8; i++) {
            const int lin = i * THREADS + tid;        // 0..1023 float4s
            const int row = lin >> 5;                 // 32 float4 per row
            const int c4  = lin & 31;
            const int col = nblk + c4 * 4;
            const size_t addr = (size_t)row * NDIM + col;

            float4 s = *reinterpret_cast<const float4*>(&g_partial[0][addr]);
#pragma unroll
            for (int p = 1; p < KSPLIT; p++) {
                const float4 q = *reinterpret_cast<const float4*>(&g_partial[p][addr]);
                s.x += q.x; s.y += q.y; s.z += q.z; s.w += q.w;
            }
            const float4 sc = *reinterpret_cast<const float4*>(scale + col);
            float4 o;
            o.x = __half2float(__float2half_rn(s.x * sc.x));
            o.y = __half2float(__float2half_rn(s.y * sc.y));
            o.z = __half2float(__float2half_rn(s.z * sc.z));
            o.w = __half2float(__float2half_rn(s.w * sc.w));
            *reinterpret_cast<float4*>(out + addr) = o;
        }
        if (tid == 0) g_counter[blockIdx.x] = 0;   // reset for next graph replay
    }
}

// ---------------------------------------------------------------------------
extern "C" void kernel_launch(void* const* d_in, const int* in_sizes, int n_in,
                              void* d_out, int out_size) {
    const float* act    = (const float*)d_in[0];   // [32, 8192] f32
    const int*   weight = (const int*)d_in[1];     // [8192, 28672] int32
    const float* scale  = (const float*)d_in[2];   // [28672] f32
    float*       out    = (float*)d_out;           // [32, 28672] f32

    dim3 grid(NBLOCKS, KSPLIT);
    dq_gemm_kernel<<<grid, THREADS>>>(act, weight, scale, out);
}